// round 13
// baseline (speedup 1.0000x reference)
#include <cuda_runtime.h>
#include <cstdint>

// NeighborPoolingLayer: out[m, :] = mean_{e in [splits[m], splits[m+1])} feat[nidx[e], :]
// feat: [N, 64] f32; nidx: [E] int32; splits: [M+1] int32; out: [M, 64] f32
//
// R8: 131.6us, DRAM-BW-bound (75.8% DRAM, L2 gather hit only ~31%).
// R10 lesson: inline .L2::evict_last needs 256-bit loads on sm_103a ptxas.
// R11-R13: use createpolicy.fractional.L2::evict_last + ld...L2::cache_hint on
// the feature-table gathers; keep .cs (streaming) on index reads + output stores.

static constexpr int C2 = 32;  // 64 floats = 32 float2 per row

__device__ __forceinline__ uint64_t make_evict_last_policy() {
    uint64_t policy;
    asm("createpolicy.fractional.L2::evict_last.b64 %0, 1.0;" : "=l"(policy));
    return policy;
}

__device__ __forceinline__ float2 ldg_table(const float2* p, uint64_t policy) {
    float2 v;
    asm("ld.global.nc.L2::cache_hint.v2.f32 {%0,%1}, [%2], %3;"
        : "=f"(v.x), "=f"(v.y) : "l"(p), "l"(policy));
    return v;
}

__device__ __forceinline__ int ldg_stream_i32(const int* p) {
    int v;
    asm("ld.global.cs.s32 %0, [%1];" : "=r"(v) : "l"(p));
    return v;
}

__device__ __forceinline__ void stg_stream(float2* p, float2 v) {
    asm volatile("st.global.cs.v2.f32 [%0], {%1,%2};"
                 :: "l"(p), "f"(v.x), "f"(v.y) : "memory");
}

__global__ __launch_bounds__(256) void neighbor_pool_kernel(
    const float2* __restrict__ feat2,        // [N, 32] as float2
    const int* __restrict__ nidx,            // [E]
    const int* __restrict__ splits,          // [M+1]
    float2* __restrict__ out2,               // [M, 32] as float2
    int M)
{
    const int warp = (blockIdx.x * blockDim.x + threadIdx.x) >> 5;
    const int lane = threadIdx.x & 31;
    if (warp >= M) return;

    const uint64_t policy = make_evict_last_policy();

    const int start = splits[warp];
    const int end   = splits[warp + 1];
    const int count = end - start;

    float accx = 0.0f, accy = 0.0f;

    int e = start;
    // Unrolled by 4 (x2 outer): up to 8 independent gathered loads in flight.
    #pragma unroll 2
    for (; e + 4 <= end; e += 4) {
        const int i0 = ldg_stream_i32(nidx + e + 0) * C2 + lane;
        const int i1 = ldg_stream_i32(nidx + e + 1) * C2 + lane;
        const int i2 = ldg_stream_i32(nidx + e + 2) * C2 + lane;
        const int i3 = ldg_stream_i32(nidx + e + 3) * C2 + lane;
        const float2 a = ldg_table(feat2 + i0, policy);
        const float2 b = ldg_table(feat2 + i1, policy);
        const float2 c = ldg_table(feat2 + i2, policy);
        const float2 d = ldg_table(feat2 + i3, policy);
        accx += (a.x + b.x) + (c.x + d.x);
        accy += (a.y + b.y) + (c.y + d.y);
    }
    for (; e < end; ++e) {
        const int i = ldg_stream_i32(nidx + e) * C2 + lane;
        const float2 a = ldg_table(feat2 + i, policy);
        accx += a.x;
        accy += a.y;
    }

    const float inv = (count > 0) ? (1.0f / (float)count) : 0.0f;
    float2 r;
    r.x = accx * inv;
    r.y = accy * inv;
    stg_stream(out2 + (size_t)warp * C2 + lane, r);
}

extern "C" void kernel_launch(void* const* d_in, const int* in_sizes, int n_in,
                              void* d_out, int out_size)
{
    const float* feat   = (const float*)d_in[0];   // [N*64] f32
    const int*   nidx   = (const int*)d_in[1];     // [E] int32
    const int*   splits = (const int*)d_in[2];     // [M+1] int32
    float*       out    = (float*)d_out;           // [M*64] f32

    const int M = in_sizes[2] - 1;

    const int threads = 256;                 // 8 warps/block
    const int warps_per_block = threads / 32;
    const int blocks = (M + warps_per_block - 1) / warps_per_block;

    neighbor_pool_kernel<<<blocks, threads>>>(
        (const float2*)feat, nidx, splits, (float2*)out, M);
}

// round 16
// speedup vs baseline: 1.0028x; 1.0028x over previous
#include <cuda_runtime.h>
#include <cstdint>

// NeighborPoolingLayer: out[m, :] = mean_{e in [splits[m], splits[m+1])} feat[nidx[e], :]
// feat: [N, 64] f32; nidx: [E] int32; splits: [M+1] int32; out: [M, 64] f32
//
// R8  (131.6us): plain __ldg gathers. DRAM-BW-bound, gather L2 hit ~31%.
// R13 (147.9us): evict_last-pinning the whole 256MB table REGRESSED — full-set
//                protection thrashes L2. Reverted.
// R14-R16: table gathers back to plain __ldg (default policy); keep ONLY the
//      streaming (.cs, evict-first) hints on the read-once index stream and
//      write-once output stream so they stop polluting L2 (~50MB of capacity).

static constexpr int C2 = 32;  // 64 floats = 32 float2 per row

__device__ __forceinline__ int ldg_stream_i32(const int* p) {
    int v;
    asm("ld.global.cs.s32 %0, [%1];" : "=r"(v) : "l"(p));
    return v;
}

__device__ __forceinline__ void stg_stream(float2* p, float2 v) {
    asm volatile("st.global.cs.v2.f32 [%0], {%1,%2};"
                 :: "l"(p), "f"(v.x), "f"(v.y) : "memory");
}

__global__ __launch_bounds__(256) void neighbor_pool_kernel(
    const float2* __restrict__ feat2,        // [N, 32] as float2
    const int* __restrict__ nidx,            // [E]
    const int* __restrict__ splits,          // [M+1]
    float2* __restrict__ out2,               // [M, 32] as float2
    int M)
{
    const int warp = (blockIdx.x * blockDim.x + threadIdx.x) >> 5;
    const int lane = threadIdx.x & 31;
    if (warp >= M) return;

    const int start = splits[warp];
    const int end   = splits[warp + 1];
    const int count = end - start;

    float accx = 0.0f, accy = 0.0f;

    int e = start;
    // Unrolled by 4 (x2 outer): up to 8 independent gathered loads in flight.
    #pragma unroll 2
    for (; e + 4 <= end; e += 4) {
        const int i0 = ldg_stream_i32(nidx + e + 0) * C2 + lane;
        const int i1 = ldg_stream_i32(nidx + e + 1) * C2 + lane;
        const int i2 = ldg_stream_i32(nidx + e + 2) * C2 + lane;
        const int i3 = ldg_stream_i32(nidx + e + 3) * C2 + lane;
        const float2 a = __ldg(feat2 + i0);
        const float2 b = __ldg(feat2 + i1);
        const float2 c = __ldg(feat2 + i2);
        const float2 d = __ldg(feat2 + i3);
        accx += (a.x + b.x) + (c.x + d.x);
        accy += (a.y + b.y) + (c.y + d.y);
    }
    for (; e < end; ++e) {
        const int i = ldg_stream_i32(nidx + e) * C2 + lane;
        const float2 a = __ldg(feat2 + i);
        accx += a.x;
        accy += a.y;
    }

    const float inv = (count > 0) ? (1.0f / (float)count) : 0.0f;
    float2 r;
    r.x = accx * inv;
    r.y = accy * inv;
    stg_stream(out2 + (size_t)warp * C2 + lane, r);
}

extern "C" void kernel_launch(void* const* d_in, const int* in_sizes, int n_in,
                              void* d_out, int out_size)
{
    const float* feat   = (const float*)d_in[0];   // [N*64] f32
    const int*   nidx   = (const int*)d_in[1];     // [E] int32
    const int*   splits = (const int*)d_in[2];     // [M+1] int32
    float*       out    = (float*)d_out;           // [M*64] f32

    const int M = in_sizes[2] - 1;

    const int threads = 256;                 // 8 warps/block
    const int warps_per_block = threads / 32;
    const int blocks = (M + warps_per_block - 1) / warps_per_block;

    neighbor_pool_kernel<<<blocks, threads>>>(
        (const float2*)feat, nidx, splits, (float2*)out, M);
}